// round 2
// baseline (speedup 1.0000x reference)
#include <cuda_runtime.h>
#include <math.h>

#define WARPS_PER_BLOCK 8
#define THREADS_PER_BLOCK (WARPS_PER_BLOCK * 32)
#define FULL_MASK 0xffffffffu

// Runtime flag: 1 if row_ptr/col_idx are int64, 0 if int32.
// JAX silently downcasts int64->int32 unless jax_enable_x64 is set, so we
// detect the actual width from the raw bytes of row_ptr (valid CSR with
// uniform degree: element 1 == DEGREE, element 0 == 0).
__device__ int g_idx_is_64 = 0;

__global__ void detect_index_width_kernel(const unsigned int* __restrict__ row_ptr_raw)
{
    // int32 layout: [0, 16, 32, ...] -> raw[1] == 16
    // int64 layout: [0,0, 16,0, 32,0, ...] -> raw[1] == 0, raw[2] == 16
    g_idx_is_64 = (row_ptr_raw[1] == 0u && row_ptr_raw[2] != 0u) ? 1 : 0;
}

__device__ __forceinline__ long long load_index(const void* p, long long i, int is64)
{
    return is64 ? ((const long long*)p)[i] : (long long)((const int*)p)[i];
}

// One warp per destination node.
// Softmax over the node's edges, then weighted gather-accumulate of 64-float
// feature rows. Each lane owns 2 feature columns (float2): each edge's gather
// is one coalesced 256B warp transaction (source is L2-resident: 25.6MB).
__global__ void __launch_bounds__(THREADS_PER_BLOCK)
gat_aggregate_kernel(const void*   __restrict__ row_ptr_raw,
                     const void*   __restrict__ col_idx_raw,
                     const float*  __restrict__ edge_scores,
                     const float2* __restrict__ node_value2,  // [N, 32] float2
                     float2*       __restrict__ out2,         // [N, 32] float2
                     int num_nodes)
{
    const int node = blockIdx.x * WARPS_PER_BLOCK + (threadIdx.x >> 5);
    if (node >= num_nodes) return;
    const int lane = threadIdx.x & 31;
    const int is64 = g_idx_is_64;  // uniform

    const long long start = load_index(row_ptr_raw, node, is64);
    const long long end   = load_index(row_ptr_raw, node + 1, is64);
    const int deg = (int)(end - start);

    float2 acc = make_float2(0.0f, 0.0f);

    if (deg == 16) {
        // ---- fast path: degree exactly 16 (this dataset) ----
        float s = -INFINITY;
        int   c = 0;
        if (lane < 16) {
            s = edge_scores[start + lane];
            c = (int)load_index(col_idx_raw, start + lane, is64);
        }
        float m = s;
        #pragma unroll
        for (int off = 8; off > 0; off >>= 1)
            m = fmaxf(m, __shfl_xor_sync(FULL_MASK, m, off));

        float w = (lane < 16) ? __expf(s - m) : 0.0f;
        float sum = w;
        #pragma unroll
        for (int off = 8; off > 0; off >>= 1)
            sum += __shfl_xor_sync(FULL_MASK, sum, off);

        w *= __frcp_rn(sum);

        // broadcast (w, col) per edge; fully unrolled -> 16 independent
        // gather loads in flight (hide L2 latency)
        #pragma unroll
        for (int e = 0; e < 16; e++) {
            const float bw = __shfl_sync(FULL_MASK, w, e);
            const int   bc = __shfl_sync(FULL_MASK, c, e);
            const float2 v = node_value2[(long long)bc * 32 + lane];
            acc.x = fmaf(bw, v.x, acc.x);
            acc.y = fmaf(bw, v.y, acc.y);
        }
    } else if (deg > 0) {
        // ---- generic path: any degree (not taken on this dataset) ----
        float m = -INFINITY;
        for (int e = lane; e < deg; e += 32)
            m = fmaxf(m, edge_scores[start + e]);
        #pragma unroll
        for (int off = 16; off > 0; off >>= 1)
            m = fmaxf(m, __shfl_xor_sync(FULL_MASK, m, off));

        float sum = 0.0f;
        for (int e = lane; e < deg; e += 32)
            sum += __expf(edge_scores[start + e] - m);
        #pragma unroll
        for (int off = 16; off > 0; off >>= 1)
            sum += __shfl_xor_sync(FULL_MASK, sum, off);
        const float inv = __frcp_rn(sum);

        for (int e = 0; e < deg; e++) {
            const float bs = edge_scores[start + e];
            const int   bc = (int)load_index(col_idx_raw, start + e, is64);
            const float bw = __expf(bs - m) * inv;
            const float2 v = node_value2[(long long)bc * 32 + lane];
            acc.x = fmaf(bw, v.x, acc.x);
            acc.y = fmaf(bw, v.y, acc.y);
        }
    }
    // deg == 0 -> zeros

    out2[(long long)node * 32 + lane] = acc;
}

extern "C" void kernel_launch(void* const* d_in, const int* in_sizes, int n_in,
                              void* d_out, int out_size)
{
    const void*  row_ptr     = d_in[0];
    const void*  col_idx     = d_in[1];
    const float* edge_scores = (const float*)d_in[2];
    const float2* node_value2 = (const float2*)d_in[3];
    float2*      out2        = (float2*)d_out;

    const int num_nodes = in_sizes[0] - 1;
    const int grid = (num_nodes + WARPS_PER_BLOCK - 1) / WARPS_PER_BLOCK;

    detect_index_width_kernel<<<1, 1>>>((const unsigned int*)row_ptr);
    gat_aggregate_kernel<<<grid, THREADS_PER_BLOCK>>>(
        row_ptr, col_idx, edge_scores, node_value2, out2, num_nodes);
}

// round 3
// speedup vs baseline: 1.0896x; 1.0896x over previous
#include <cuda_runtime.h>
#include <math.h>

#define WARPS_PER_BLOCK 8
#define THREADS_PER_BLOCK (WARPS_PER_BLOCK * 32)
#define FULL_MASK 0xffffffffu

// Index width (int32 vs int64) is detected inside the kernel from the raw
// words of row_ptr: valid CSR with row_ptr[0]==0 and row_ptr[1]==DEGREE>0.
//   int32 layout: [0, D, 2D, ...]   -> raw[1] != 0
//   int64 layout: [0,0, D,0, ...]   -> raw[1] == 0, raw[2] != 0
__device__ __forceinline__ long long load_index(const void* p, long long i, int is64)
{
    return is64 ? ((const long long*)p)[i] : (long long)((const int*)p)[i];
}

// One warp per destination node. Softmax over 16 edge scores, then weighted
// gather-accumulate of 64-float rows. Gather uses float4: 16 lanes cover one
// row, the two half-warps process two edges per iteration (8 LDG.128/node).
__global__ void __launch_bounds__(THREADS_PER_BLOCK)
gat_aggregate_kernel(const void*   __restrict__ row_ptr_raw,
                     const void*   __restrict__ col_idx_raw,
                     const float*  __restrict__ edge_scores,
                     const float4* __restrict__ node_value4,  // [N, 16] float4
                     float4*       __restrict__ out4,         // [N, 16] float4
                     int num_nodes)
{
    const int node = blockIdx.x * WARPS_PER_BLOCK + (threadIdx.x >> 5);
    if (node >= num_nodes) return;
    const int lane = threadIdx.x & 31;

    // uniform per-grid: detect index width from raw row_ptr words (L2 broadcast)
    const unsigned* rp_raw = (const unsigned*)row_ptr_raw;
    const int is64 = (rp_raw[1] == 0u && rp_raw[2] != 0u) ? 1 : 0;

    const long long start = load_index(row_ptr_raw, node, is64);
    const long long end   = load_index(row_ptr_raw, node + 1, is64);
    const int deg = (int)(end - start);

    const int half = lane >> 4;    // 0 or 1: which half-warp
    const int sub  = lane & 15;    // float4 column within the row

    float4 acc = make_float4(0.0f, 0.0f, 0.0f, 0.0f);

    if (deg == 16) {
        // ---- fast path: degree exactly 16 (this dataset) ----
        float s = -INFINITY;
        unsigned c = 0;
        if (lane < 16) {
            s = edge_scores[start + lane];
            c = (unsigned)load_index(col_idx_raw, start + lane, is64);
        }
        float m = s;
        #pragma unroll
        for (int off = 8; off > 0; off >>= 1)
            m = fmaxf(m, __shfl_xor_sync(FULL_MASK, m, off));

        float w = (lane < 16) ? __expf(s - m) : 0.0f;
        float sum = w;
        #pragma unroll
        for (int off = 8; off > 0; off >>= 1)
            sum += __shfl_xor_sync(FULL_MASK, sum, off);

        w *= __frcp_rn(sum);

        // two edges per iteration: half-warp h takes edge 2*e+h.
        // 8 fully-unrolled LDG.128 -> deep MLP, half the instruction count.
        #pragma unroll
        for (int e = 0; e < 8; e++) {
            const int edge = 2 * e + half;
            const float    bw = __shfl_sync(FULL_MASK, w, edge);
            const unsigned bc = __shfl_sync(FULL_MASK, c, edge);
            const float4 v = node_value4[(size_t)bc * 16 + sub];
            acc.x = fmaf(bw, v.x, acc.x);
            acc.y = fmaf(bw, v.y, acc.y);
            acc.z = fmaf(bw, v.z, acc.z);
            acc.w = fmaf(bw, v.w, acc.w);
        }

        // combine the two half-warp partial sums
        acc.x += __shfl_xor_sync(FULL_MASK, acc.x, 16);
        acc.y += __shfl_xor_sync(FULL_MASK, acc.y, 16);
        acc.z += __shfl_xor_sync(FULL_MASK, acc.z, 16);
        acc.w += __shfl_xor_sync(FULL_MASK, acc.w, 16);

        if (half == 0)
            out4[(size_t)node * 16 + sub] = acc;
    } else {
        // ---- generic path: any degree (not taken on this dataset) ----
        float m = -INFINITY;
        for (int e = lane; e < deg; e += 32)
            m = fmaxf(m, edge_scores[start + e]);
        #pragma unroll
        for (int off = 16; off > 0; off >>= 1)
            m = fmaxf(m, __shfl_xor_sync(FULL_MASK, m, off));

        float sum = 0.0f;
        for (int e = lane; e < deg; e += 32)
            sum += __expf(edge_scores[start + e] - m);
        #pragma unroll
        for (int off = 16; off > 0; off >>= 1)
            sum += __shfl_xor_sync(FULL_MASK, sum, off);
        const float inv = (deg > 0) ? __frcp_rn(sum) : 0.0f;

        for (int e = half; e < deg; e += 2) {
            const float bs = edge_scores[start + e];
            const unsigned bc = (unsigned)load_index(col_idx_raw, start + e, is64);
            const float bw = __expf(bs - m) * inv;
            const float4 v = node_value4[(size_t)bc * 16 + sub];
            acc.x = fmaf(bw, v.x, acc.x);
            acc.y = fmaf(bw, v.y, acc.y);
            acc.z = fmaf(bw, v.z, acc.z);
            acc.w = fmaf(bw, v.w, acc.w);
        }
        acc.x += __shfl_xor_sync(FULL_MASK, acc.x, 16);
        acc.y += __shfl_xor_sync(FULL_MASK, acc.y, 16);
        acc.z += __shfl_xor_sync(FULL_MASK, acc.z, 16);
        acc.w += __shfl_xor_sync(FULL_MASK, acc.w, 16);

        if (half == 0)
            out4[(size_t)node * 16 + sub] = acc;
    }
}

extern "C" void kernel_launch(void* const* d_in, const int* in_sizes, int n_in,
                              void* d_out, int out_size)
{
    const void*   row_ptr     = d_in[0];
    const void*   col_idx     = d_in[1];
    const float*  edge_scores = (const float*)d_in[2];
    const float4* node_value4 = (const float4*)d_in[3];
    float4*       out4        = (float4*)d_out;

    const int num_nodes = in_sizes[0] - 1;
    const int grid = (num_nodes + WARPS_PER_BLOCK - 1) / WARPS_PER_BLOCK;

    gat_aggregate_kernel<<<grid, THREADS_PER_BLOCK>>>(
        row_ptr, col_idx, edge_scores, node_value4, out4, num_nodes);
}